// round 12
// baseline (speedup 1.0000x reference)
#include <cuda_runtime.h>
#include <cuda_bf16.h>
#include <math.h>
#include <cstdint>

#define BB 2
#define SS 2048
#define DD 1024
#define HH 16
#define DH 64
#define MROWS (BB*SS)   // 4096

// fp32 scratch
__device__ float g_Q[BB*HH*SS*DH];    // Q natural [bh][s][d] (attn Q staging)
// bf16 split operands for attention
__device__ __nv_bfloat16 g_Khi[BB*HH*SS*DH];  // fused K, natural [bh][s][d]
__device__ __nv_bfloat16 g_Klo[BB*HH*SS*DH];
__device__ __nv_bfloat16 g_Vhi[BB*HH*DH*SS];  // V(=Q) transposed [bh][d][s]
__device__ __nv_bfloat16 g_Vlo[BB*HH*DH*SS];
// bf16 split operands for projections
__device__ __nv_bfloat16 g_Ahi[MROWS*DD];     // hidden_states [m][k]
__device__ __nv_bfloat16 g_Alo[MROWS*DD];
__device__ __nv_bfloat16 g_Wthi[2*DD*DD];     // W transposed [w][n][k]
__device__ __nv_bfloat16 g_Wtlo[2*DD*DD];

__device__ __forceinline__ float logsig(float x) {
    return fminf(x, 0.0f) - log1pf(expf(-fabsf(x)));
}

// ---- mma.sync / ldmatrix / cp.async helpers (sm_80+ PTX) ------------------
__device__ __forceinline__ uint32_t smem_u32(const void* p) {
    uint32_t a;
    asm("{ .reg .u64 t; cvta.to.shared.u64 t, %1; cvt.u32.u64 %0, t; }" : "=r"(a) : "l"(p));
    return a;
}
__device__ __forceinline__ void ldsm4(uint32_t* r, uint32_t addr) {
    asm volatile("ldmatrix.sync.aligned.m8n8.x4.shared.b16 {%0,%1,%2,%3}, [%4];"
        : "=r"(r[0]), "=r"(r[1]), "=r"(r[2]), "=r"(r[3]) : "r"(addr));
}
__device__ __forceinline__ void mma16816(float* c, const uint32_t* a, const uint32_t* b) {
    asm volatile(
        "mma.sync.aligned.m16n8k16.row.col.f32.bf16.bf16.f32 "
        "{%0,%1,%2,%3}, {%4,%5,%6,%7}, {%8,%9}, {%0,%1,%2,%3};"
        : "+f"(c[0]), "+f"(c[1]), "+f"(c[2]), "+f"(c[3])
        : "r"(a[0]), "r"(a[1]), "r"(a[2]), "r"(a[3]), "r"(b[0]), "r"(b[1]));
}
__device__ __forceinline__ void split_pair(float x, float y, uint32_t& hi, uint32_t& lo) {
    __nv_bfloat16 hx = __float2bfloat16(x), hy = __float2bfloat16(y);
    __nv_bfloat16 lx = __float2bfloat16(x - __bfloat162float(hx));
    __nv_bfloat16 ly = __float2bfloat16(y - __bfloat162float(hy));
    __nv_bfloat162 hv; hv.x = hx; hv.y = hy;
    __nv_bfloat162 lv; lv.x = lx; lv.y = ly;
    hi = *(const uint32_t*)&hv;
    lo = *(const uint32_t*)&lv;
}
__device__ __forceinline__ void cpasync16(uint32_t saddr, const void* g) {
    asm volatile("cp.async.cg.shared.global [%0], [%1], 16;" :: "r"(saddr), "l"(g));
}
#define CP_COMMIT()     asm volatile("cp.async.commit_group;" ::: "memory")
#define CP_WAIT(n)      asm volatile("cp.async.wait_group %0;" :: "n"(n) : "memory")

// ---------------------------------------------------------------------------
// split_hs: hidden_states fp32 [m][k] -> bf16 hi/lo. 8 elems/thread.
// ---------------------------------------------------------------------------
__global__ __launch_bounds__(256) void split_hs(const float* __restrict__ hs)
{
    const int i8 = blockIdx.x * 256 + threadIdx.x;
    float4 a = ((const float4*)hs)[i8*2];
    float4 b = ((const float4*)hs)[i8*2+1];
    float f[8] = { a.x,a.y,a.z,a.w, b.x,b.y,b.z,b.w };
    __nv_bfloat16 hi[8], lo[8];
    #pragma unroll
    for (int j = 0; j < 8; j++) {
        hi[j] = __float2bfloat16(f[j]);
        lo[j] = __float2bfloat16(f[j] - __bfloat162float(hi[j]));
    }
    ((uint4*)g_Ahi)[i8] = *(const uint4*)hi;
    ((uint4*)g_Alo)[i8] = *(const uint4*)lo;
}

// ---------------------------------------------------------------------------
// split_w: W fp32 [k][n] -> Wt bf16 hi/lo [n][k]. 64x64 tiles, 256 threads.
// ---------------------------------------------------------------------------
__global__ __launch_bounds__(256) void split_w(
    const float* __restrict__ Wq, const float* __restrict__ Wk)
{
    __shared__ float tw[64][65];
    const int wsel = blockIdx.z;
    const float* W = wsel ? Wk : Wq;
    const int k0 = blockIdx.y * 64;
    const int n0 = blockIdx.x * 64;
    const int tid = threadIdx.x;

    #pragma unroll
    for (int i = 0; i < 4; i++) {
        int idx4 = tid + i * 256;
        int row  = idx4 >> 4;
        int c    = (idx4 & 15) * 4;
        float4 v = *(const float4*)&W[(size_t)(k0 + row) * DD + n0 + c];
        tw[row][c+0] = v.x; tw[row][c+1] = v.y; tw[row][c+2] = v.z; tw[row][c+3] = v.w;
    }
    __syncthreads();

    const int n  = tid >> 2;
    const int kq = (tid & 3) * 16;
    __nv_bfloat16 hi[16], lo[16];
    #pragma unroll
    for (int c = 0; c < 16; c++) {
        float v = tw[kq+c][n];
        hi[c] = __float2bfloat16(v);
        lo[c] = __float2bfloat16(v - __bfloat162float(hi[c]));
    }
    size_t off = (size_t)wsel*DD*DD + (size_t)(n0 + n)*DD + k0 + kq;
    *(uint4*)(g_Wthi + off)     = *(const uint4*)hi;
    *(uint4*)(g_Wthi + off + 8) = *(const uint4*)(hi + 8);
    *(uint4*)(g_Wtlo + off)     = *(const uint4*)lo;
    *(uint4*)(g_Wtlo + off + 8) = *(const uint4*)(lo + 8);
}

// ---------------------------------------------------------------------------
// Fused projection: one block computes BOTH Q and K for its 128m x 128n tile
// (two pipelined passes), then fuses all epilogue work:
//   pass1 -> g_Q + qres(smem);  transpose qres -> g_Vhi/g_Vlo;
//   pass2 -> k; fused logsig epilogue -> g_Khi/g_Klo.
// smem: 2 stages x (AH|AL|BH|BL = 64KB) + qres fp32 128x130 = ~193KB.
// ---------------------------------------------------------------------------
#define PF_AH 0
#define PF_AL 16384
#define PF_BH 32768
#define PF_BL 49152
#define PF_STAGE 65536
#define PF_QRES (2*PF_STAGE)                 // fp32 [128][130]
#define PF_SMEM (PF_QRES + 128*130*4)        // 197632 B

__global__ __launch_bounds__(256) void proj_fused(
    const float* __restrict__ bq, const float* __restrict__ bk)
{
    extern __shared__ char smem[];
    const uint32_t sb = smem_u32(smem);
    float* qres = (float*)(smem + PF_QRES);
    const int tid  = threadIdx.x;
    const int w    = tid >> 5;
    const int lane = tid & 31;
    const int m0 = blockIdx.y * 128;
    const int n0 = blockIdx.x * 128;

    const uint4* Ahi = (const uint4*)g_Ahi;
    const uint4* Alo = (const uint4*)g_Alo;

    const int row_off = (lane & 7) + ((lane & 16) >> 1);
    const int khalf   = (lane >> 3) & 1;
    const int arow    = lane & 15;
    const int ahalf   = (lane >> 4) & 1;

    int srow[4], sck[4]; uint32_t soff[4];
    #pragma unroll
    for (int i = 0; i < 4; i++) {
        int c = tid + i * 256;
        srow[i] = c >> 3; sck[i] = c & 7;
        soff[i] = (uint32_t)(srow[i] * 128 + ((sck[i] ^ (srow[i] & 7)) << 4));
    }

    const int lm0 = w * 16 + (lane >> 2);    // local m row (0..127)
    const int cq  = (lane & 3) * 2;
    const int bb  = m0 >> 11;
    const int s0g = m0 & (SS - 1);

    // ---- one pipelined GEMM pass over K=1024 ----
    auto run_pass = [&](const uint4* Bhi, const uint4* Blo, float acc[16][4]) {
        auto issue_stage = [&](int k0, int buf) {
            const uint32_t base = sb + buf * PF_STAGE;
            #pragma unroll
            for (int i = 0; i < 4; i++) {
                int asrc = (m0 + srow[i]) * (DD/8) + k0/8 + sck[i];
                cpasync16(base + PF_AH + soff[i], Ahi + asrc);
                cpasync16(base + PF_AL + soff[i], Alo + asrc);
                int bsrc = (n0 + srow[i]) * (DD/8) + k0/8 + sck[i];
                cpasync16(base + PF_BH + soff[i], Bhi + bsrc);
                cpasync16(base + PF_BL + soff[i], Blo + bsrc);
            }
        };

        issue_stage(0, 0);
        CP_COMMIT();

        for (int t = 0; t < 16; t++) {
            if (t < 15) {
                issue_stage((t + 1) * 64, (t + 1) & 1);
                CP_COMMIT();
                CP_WAIT(1);
            } else {
                CP_WAIT(0);
            }
            __syncthreads();

            const uint32_t base = sb + (t & 1) * PF_STAGE;
            #pragma unroll
            for (int ks = 0; ks < 4; ks++) {
                int ar = w * 16 + arow;
                int ac = ks * 2 + ahalf;
                uint32_t aoff = (uint32_t)(ar * 128 + ((ac ^ (ar & 7)) << 4));
                uint32_t ah4[4], al4[4];
                ldsm4(ah4, base + PF_AH + aoff);
                ldsm4(al4, base + PF_AL + aoff);

                #pragma unroll
                for (int jp = 0; jp < 8; jp++) {
                    int br = jp * 16 + row_off;
                    int bc = ks * 2 + khalf;
                    uint32_t boff = (uint32_t)(br * 128 + ((bc ^ (br & 7)) << 4));
                    uint32_t bh4[4], bl4[4];
                    ldsm4(bh4, base + PF_BH + boff);
                    ldsm4(bl4, base + PF_BL + boff);
                    mma16816(acc[2*jp],   ah4, bh4);
                    mma16816(acc[2*jp],   al4, bh4);
                    mma16816(acc[2*jp],   ah4, bl4);
                    mma16816(acc[2*jp+1], ah4, bh4 + 2);
                    mma16816(acc[2*jp+1], al4, bh4 + 2);
                    mma16816(acc[2*jp+1], ah4, bl4 + 2);
                }
            }
            __syncthreads();
        }
    };

    // ================= pass 1: Q =================
    {
        float acc[16][4];
        #pragma unroll
        for (int j = 0; j < 16; j++)
            #pragma unroll
            for (int c = 0; c < 4; c++) acc[j][c] = 0.0f;

        run_pass((const uint4*)g_Wthi, (const uint4*)g_Wtlo, acc);

        // epilogue: q -> g_Q + qres
        #pragma unroll
        for (int j = 0; j < 16; j++) {
            int n = j * 8 + cq;
            int ng = n0 + n;
            int h = ng >> 6, d = ng & (DH - 1);
            float q0v = acc[j][0] + bq[ng], q1v = acc[j][1] + bq[ng+1];
            float q2v = acc[j][2] + bq[ng], q3v = acc[j][3] + bq[ng+1];
            qres[lm0*130 + n]     = q0v; qres[lm0*130 + n + 1]     = q1v;
            qres[(lm0+8)*130 + n] = q2v; qres[(lm0+8)*130 + n + 1] = q3v;
            *(float2*)&g_Q[(((size_t)bb * HH + h) * SS + s0g + lm0)     * DH + d] = make_float2(q0v, q1v);
            *(float2*)&g_Q[(((size_t)bb * HH + h) * SS + s0g + lm0 + 8) * DH + d] = make_float2(q2v, q3v);
        }
    }
    __syncthreads();   // qres complete

    // ---- V^T: qres columns -> g_Vhi/g_Vlo [bh][d][s] (split) ----
    {
        const int trow = tid >> 1;            // 0..127: block-local n
        const int h2 = trow >> 6, d = trow & 63;
        const int ss0 = (tid & 1) * 64;
        uint32_t hib[32], lob[32];
        #pragma unroll
        for (int i = 0; i < 32; i++) {
            float x = qres[(ss0 + 2*i)     * 130 + trow];
            float y = qres[(ss0 + 2*i + 1) * 130 + trow];
            split_pair(x, y, hib[i], lob[i]);
        }
        size_t vbase = ((size_t)(bb * HH + (n0 >> 6) + h2)) * DH * SS
                     + (size_t)d * SS + s0g + ss0;
        #pragma unroll
        for (int i = 0; i < 8; i++) {
            ((uint4*)(g_Vhi + vbase))[i] = ((const uint4*)hib)[i];
            ((uint4*)(g_Vlo + vbase))[i] = ((const uint4*)lob)[i];
        }
    }
    // no sync needed: pass 2 only writes stage buffers; qres is read-only below

    // ================= pass 2: K =================
    {
        float acc[16][4];
        #pragma unroll
        for (int j = 0; j < 16; j++)
            #pragma unroll
            for (int c = 0; c < 4; c++) acc[j][c] = 0.0f;

        run_pass((const uint4*)(g_Wthi + (size_t)DD*DD),
                 (const uint4*)(g_Wtlo + (size_t)DD*DD), acc);

        // epilogue: fused logsig K -> g_Khi/g_Klo
        #pragma unroll
        for (int j = 0; j < 16; j++) {
            int n = j * 8 + cq;
            int ng = n0 + n;
            int h = ng >> 6, d = ng & (DH - 1);
            float bk0 = bk[ng], bk1 = bk[ng+1];

            float q0v = qres[lm0*130 + n],     q1v = qres[lm0*130 + n + 1];
            float q2v = qres[(lm0+8)*130 + n], q3v = qres[(lm0+8)*130 + n + 1];
            float f0 = logsig(logsig(q0v) + q0v + acc[j][0] + bk0);
            float f1 = logsig(logsig(q1v) + q1v + acc[j][1] + bk1);
            float f2 = logsig(logsig(q2v) + q2v + acc[j][2] + bk0);
            float f3 = logsig(logsig(q3v) + q3v + acc[j][3] + bk1);

            uint32_t h01, l01, h23, l23;
            split_pair(f0, f1, h01, l01);
            split_pair(f2, f3, h23, l23);
            size_t o0 = (((size_t)bb * HH + h) * SS + s0g + lm0)     * DH + d;
            size_t o1 = (((size_t)bb * HH + h) * SS + s0g + lm0 + 8) * DH + d;
            *(uint32_t*)&g_Khi[o0] = h01; *(uint32_t*)&g_Klo[o0] = l01;
            *(uint32_t*)&g_Khi[o1] = h23; *(uint32_t*)&g_Klo[o1] = l23;
        }
    }
}

// ---------------------------------------------------------------------------
// mma.sync flash attention with 2-stage cp.async pipeline (R10 — known good).
// ---------------------------------------------------------------------------
#define AT_KH 0
#define AT_KL 16384
#define AT_VH 32768
#define AT_VL 49152
#define AT_STAGE 65536
#define ATTN_SMEM (2*AT_STAGE)

__global__ __launch_bounds__(256, 1) void attn(
    const int* __restrict__ mask, float* __restrict__ out)
{
    extern __shared__ char smem[];
    const uint32_t sb = smem_u32(smem);
    const int tid  = threadIdx.x;
    const int w    = tid >> 5;
    const int lane = tid & 31;
    const int bh = blockIdx.y;
    const int b  = bh >> 4;
    const int h  = bh & (HH - 1);
    const int q0 = blockIdx.x * 128;

    const int row_off = (lane & 7) + ((lane & 16) >> 1);
    const int khalf   = (lane >> 3) & 1;

    const uint4* Khi = (const uint4*)(g_Khi + (size_t)bh * SS * DH);
    const uint4* Klo = (const uint4*)(g_Klo + (size_t)bh * SS * DH);
    const uint4* Vhi = (const uint4*)(g_Vhi + (size_t)bh * DH * SS);
    const uint4* Vlo = (const uint4*)(g_Vlo + (size_t)bh * DH * SS);

    int krow[4], kck[4]; uint32_t koff[4];
    int vrow[4], vck[4]; uint32_t voff[4];
    #pragma unroll
    for (int i = 0; i < 4; i++) {
        int c = tid + i * 256;
        krow[i] = c >> 3; kck[i] = c & 7;
        koff[i] = (uint32_t)(krow[i] * 128 + ((kck[i] ^ (krow[i] & 7)) << 4));
        vrow[i] = c >> 4; vck[i] = c & 15;
        voff[i] = (uint32_t)(vrow[i] * 256 + ((vck[i] ^ (vrow[i] & 7)) << 4));
    }

    auto issue_stage = [&](int t0, int buf) {
        const uint32_t base = sb + buf * AT_STAGE;
        #pragma unroll
        for (int i = 0; i < 4; i++) {
            int ksrc = (t0 + krow[i]) * 8 + kck[i];
            cpasync16(base + AT_KH + koff[i], Khi + ksrc);
            cpasync16(base + AT_KL + koff[i], Klo + ksrc);
            int vsrc = vrow[i] * (SS/8) + t0/8 + vck[i];
            cpasync16(base + AT_VH + voff[i], Vhi + vsrc);
            cpasync16(base + AT_VL + voff[i], Vlo + vsrc);
        }
    };

    issue_stage(0, 0);
    CP_COMMIT();

    {
        float* Qs = (float*)(smem + AT_STAGE);
        const float* src = g_Q + ((size_t)bh * SS + q0) * DH;
        #pragma unroll
        for (int i = 0; i < 8; i++) {
            int idx4 = tid + i * 256;
            ((float4*)Qs)[idx4] = ((const float4*)src)[idx4];
        }
        __syncthreads();
    }

    const int r0 = lane >> 2;
    const int cq = (lane & 3) * 2;
    uint32_t qh[4][4], ql[4][4];
    {
        const float* Qs = (const float*)(smem + AT_STAGE);
        const int m0 = w * 16 + r0;
        #pragma unroll
        for (int ks = 0; ks < 4; ks++) {
            int c0 = ks * 16 + cq;
            float x0 = Qs[m0*64 + c0]     * -0.125f, y0 = Qs[m0*64 + c0 + 1]     * -0.125f;
            float x1 = Qs[(m0+8)*64 + c0] * -0.125f, y1 = Qs[(m0+8)*64 + c0 + 1] * -0.125f;
            float x2 = Qs[m0*64 + c0 + 8] * -0.125f, y2 = Qs[m0*64 + c0 + 9]     * -0.125f;
            float x3 = Qs[(m0+8)*64 + c0 + 8] * -0.125f, y3 = Qs[(m0+8)*64 + c0 + 9] * -0.125f;
            split_pair(x0, y0, qh[ks][0], ql[ks][0]);
            split_pair(x1, y1, qh[ks][1], ql[ks][1]);
            split_pair(x2, y2, qh[ks][2], ql[ks][2]);
            split_pair(x3, y3, qh[ks][3], ql[ks][3]);
        }
        __syncthreads();
    }

    const bool mq0 = (mask[b * SS + q0 + w*16 + r0]     == 0);
    const bool mq1 = (mask[b * SS + q0 + w*16 + r0 + 8] == 0);

    float l0 = 0.0f, l1 = 0.0f;
    float oacc[8][4];
    #pragma unroll
    for (int j = 0; j < 8; j++)
        #pragma unroll
        for (int c = 0; c < 4; c++) oacc[j][c] = 0.0f;

    for (int t = 0; t < 16; t++) {
        if (t < 15) {
            issue_stage((t + 1) * 128, (t + 1) & 1);
            CP_COMMIT();
            CP_WAIT(1);
        } else {
            CP_WAIT(0);
        }
        __syncthreads();

        const uint32_t base = sb + (t & 1) * AT_STAGE;

        float sacc[16][4];
        #pragma unroll
        for (int j = 0; j < 16; j++)
            #pragma unroll
            for (int c = 0; c < 4; c++) sacc[j][c] = 0.0f;

        #pragma unroll
        for (int ks = 0; ks < 4; ks++) {
            #pragma unroll
            for (int jp = 0; jp < 8; jp++) {
                int row = jp * 16 + row_off;
                int chunk = ks * 2 + khalf;
                uint32_t off = (uint32_t)(row * 128 + ((chunk ^ (row & 7)) << 4));
                uint32_t bh4[4], bl4[4];
                ldsm4(bh4, base + AT_KH + off);
                ldsm4(bl4, base + AT_KL + off);
                mma16816(sacc[2*jp],   qh[ks], bh4);
                mma16816(sacc[2*jp],   ql[ks], bh4);
                mma16816(sacc[2*jp],   qh[ks], bl4);
                mma16816(sacc[2*jp+1], qh[ks], bh4 + 2);
                mma16816(sacc[2*jp+1], ql[ks], bh4 + 2);
                mma16816(sacc[2*jp+1], qh[ks], bl4 + 2);
            }
        }

        uint32_t phi[8][4], plo[8][4];
        #pragma unroll
        for (int kp = 0; kp < 8; kp++) {
            float p[8];
            #pragma unroll
            for (int half = 0; half < 2; half++) {
                const float* sc = sacc[2*kp + half];
                p[half*4+0] = __expf(mq0 ? 0.0f : sc[0]);
                p[half*4+1] = __expf(mq0 ? 0.0f : sc[1]);
                p[half*4+2] = __expf(mq1 ? 0.0f : sc[2]);
                p[half*4+3] = __expf(mq1 ? 0.0f : sc[3]);
            }
            l0 += p[0] + p[1] + p[4] + p[5];
            l1 += p[2] + p[3] + p[6] + p[7];
            split_pair(p[0], p[1], phi[kp][0], plo[kp][0]);
            split_pair(p[2], p[3], phi[kp][1], plo[kp][1]);
            split_pair(p[4], p[5], phi[kp][2], plo[kp][2]);
            split_pair(p[6], p[7], phi[kp][3], plo[kp][3]);
        }

        #pragma unroll
        for (int kp = 0; kp < 8; kp++) {
            #pragma unroll
            for (int jp = 0; jp < 4; jp++) {
                int row = jp * 16 + row_off;
                int chunk = kp * 2 + khalf;
                uint32_t off = (uint32_t)(row * 256 + ((chunk ^ (row & 7)) << 4));
                uint32_t vh4[4], vl4[4];
                ldsm4(vh4, base + AT_VH + off);
                ldsm4(vl4, base + AT_VL + off);
                mma16816(oacc[2*jp],   phi[kp], vh4);
                mma16816(oacc[2*jp],   plo[kp], vh4);
                mma16816(oacc[2*jp],   phi[kp], vl4);
                mma16816(oacc[2*jp+1], phi[kp], vh4 + 2);
                mma16816(oacc[2*jp+1], plo[kp], vh4 + 2);
                mma16816(oacc[2*jp+1], phi[kp], vl4 + 2);
            }
        }
        __syncthreads();
    }

    l0 += __shfl_xor_sync(0xffffffffu, l0, 1);
    l0 += __shfl_xor_sync(0xffffffffu, l0, 2);
    l1 += __shfl_xor_sync(0xffffffffu, l1, 1);
    l1 += __shfl_xor_sync(0xffffffffu, l1, 2);
    const float inv0 = 1.0f / l0;
    const float inv1 = 1.0f / l1;

    const int s0 = q0 + w*16 + r0;
    float* o0 = out + ((size_t)b * SS + s0)     * (HH*DH) + h * DH;
    float* o1 = out + ((size_t)b * SS + s0 + 8) * (HH*DH) + h * DH;
    #pragma unroll
    for (int j = 0; j < 8; j++) {
        int col = j * 8 + cq;
        float2 w0 = make_float2(oacc[j][0] * inv0, oacc[j][1] * inv0);
        float2 w1 = make_float2(oacc[j][2] * inv1, oacc[j][3] * inv1);
        *(float2*)(o0 + col) = w0;
        *(float2*)(o1 + col) = w1;
    }
}

// ---------------------------------------------------------------------------
extern "C" void kernel_launch(void* const* d_in, const int* in_sizes, int n_in,
                              void* d_out, int out_size)
{
    const float* hs   = (const float*)d_in[0];
    const int*   mask = (const int*)  d_in[1];
    const float* Wq   = (const float*)d_in[2];
    const float* bq   = (const float*)d_in[3];
    const float* Wk   = (const float*)d_in[4];
    const float* bk   = (const float*)d_in[5];
    float* out = (float*)d_out;

    split_hs<<<(MROWS*DD) / (256 * 8), 256>>>(hs);
    dim3 wgrid(DD / 64, DD / 64, 2);
    split_w<<<wgrid, 256>>>(Wq, Wk);

    cudaFuncSetAttribute(proj_fused, cudaFuncAttributeMaxDynamicSharedMemorySize, PF_SMEM);
    dim3 pgrid(DD / 128, MROWS / 128);                      // (8,32)
    proj_fused<<<pgrid, 256, PF_SMEM>>>(bq, bk);

    cudaFuncSetAttribute(attn, cudaFuncAttributeMaxDynamicSharedMemorySize, ATTN_SMEM);
    dim3 agrid(SS / 128, BB * HH);                          // (16,32)
    attn<<<agrid, 256, ATTN_SMEM>>>(mask, out);
}